// round 7
// baseline (speedup 1.0000x reference)
#include <cuda_runtime.h>
#include <cuda_bf16.h>
#include <cstdint>

// Problem constants
static constexpr int Bz = 64;     // batch
static constexpr int Sz = 1024;   // seq len
static constexpr int Hz = 256;    // hidden
static constexpr int G3 = 768;    // 3*H gate rows

// Recurrence kernel geometry: 16 clusters x 4 CTAs; each cluster = 4 batches,
// each CTA owns 64 h-units (192 gate rows of W_hh in smem).
static constexpr int LDW = 260;   // padded row stride (floats) to kill bank conflicts
static constexpr int SMEM_FLOATS = 192 * LDW + 192 + 2 * 4 * LDW; // W + bias + double-buffered h
static constexpr int SMEM_BYTES = SMEM_FLOATS * 4;                // 208,768 B

// Scratch for precomputed input-side gate projections xg = x @ W_ih^T + b_ih  [B,S,3H]
__device__ float g_xg[(size_t)Bz * Sz * G3];

typedef unsigned long long u64;

__device__ __forceinline__ u64 fma2(u64 a, u64 b, u64 c) {
    u64 d;
    asm("fma.rn.f32x2 %0, %1, %2, %3;" : "=l"(d) : "l"(a), "l"(b), "l"(c));
    return d;
}
__device__ __forceinline__ float f2lo(u64 v) { return __uint_as_float((unsigned)v); }
__device__ __forceinline__ float f2hi(u64 v) { return __uint_as_float((unsigned)(v >> 32)); }
__device__ __forceinline__ u64 dup2(float a) {
    unsigned ai = __float_as_uint(a);
    u64 d;
    asm("mov.b64 %0, {%1, %2};" : "=l"(d) : "r"(ai), "r"(ai));
    return d;
}

// ---------------------------------------------------------------------------
// GEMM: g_xg[m, 0:768] = A[m, 0:256] @ W[768, 256]^T + bias
// A row-major with runtime lda (256 for layer-0 inputs, 512 for h1 inside concat out).
// Tiles 64x64, BK=32, 256 threads, 4x4 micro-tile via fma.rn.f32x2.
// ---------------------------------------------------------------------------
__global__ __launch_bounds__(256) void gemm_nt_bias(
    const float* __restrict__ A, int lda,
    const float* __restrict__ W,
    const float* __restrict__ bias)
{
    __shared__ __align__(16) float As[32][68];  // As[k][m]
    __shared__ __align__(16) float Ws[32][68];  // Ws[k][n]

    const int tid = threadIdx.x;
    const int tx = tid & 15;          // 0..15 -> 4 cols
    const int ty = tid >> 4;          // 0..15 -> 4 rows
    const int m0 = blockIdx.y * 64;
    const int n0 = blockIdx.x * 64;

    u64 c00 = 0, c01 = 0, c10 = 0, c11 = 0, c20 = 0, c21 = 0, c30 = 0, c31 = 0;

    const int lrow = tid >> 3;        // 0..31
    const int lc4  = tid & 7;         // 0..7 (float4 column within 32-wide K tile)

    for (int k0 = 0; k0 < 256; k0 += 32) {
#pragma unroll
        for (int h = 0; h < 2; ++h) {
            const int row = lrow + h * 32;
            float4 va = *(const float4*)(A + (size_t)(m0 + row) * lda + k0 + lc4 * 4);
            As[lc4 * 4 + 0][row] = va.x;
            As[lc4 * 4 + 1][row] = va.y;
            As[lc4 * 4 + 2][row] = va.z;
            As[lc4 * 4 + 3][row] = va.w;
            float4 vw = *(const float4*)(W + (size_t)(n0 + row) * 256 + k0 + lc4 * 4);
            Ws[lc4 * 4 + 0][row] = vw.x;
            Ws[lc4 * 4 + 1][row] = vw.y;
            Ws[lc4 * 4 + 2][row] = vw.z;
            Ws[lc4 * 4 + 3][row] = vw.w;
        }
        __syncthreads();
#pragma unroll 8
        for (int kk = 0; kk < 32; ++kk) {
            float4 a4 = *(const float4*)&As[kk][ty * 4];
            ulonglong2 w4 = *(const ulonglong2*)&Ws[kk][tx * 4];
            u64 d0 = dup2(a4.x), d1 = dup2(a4.y), d2 = dup2(a4.z), d3 = dup2(a4.w);
            c00 = fma2(d0, w4.x, c00); c01 = fma2(d0, w4.y, c01);
            c10 = fma2(d1, w4.x, c10); c11 = fma2(d1, w4.y, c11);
            c20 = fma2(d2, w4.x, c20); c21 = fma2(d2, w4.y, c21);
            c30 = fma2(d3, w4.x, c30); c31 = fma2(d3, w4.y, c31);
        }
        __syncthreads();
    }

    const float4 bb = *(const float4*)(bias + n0 + tx * 4);
    float* Cbase = g_xg + (size_t)(m0 + ty * 4) * G3 + n0 + tx * 4;
    {
        float4 o;
        o.x = f2lo(c00) + bb.x; o.y = f2hi(c00) + bb.y;
        o.z = f2lo(c01) + bb.z; o.w = f2hi(c01) + bb.w;
        *(float4*)(Cbase + 0 * G3) = o;
    }
    {
        float4 o;
        o.x = f2lo(c10) + bb.x; o.y = f2hi(c10) + bb.y;
        o.z = f2lo(c11) + bb.z; o.w = f2hi(c11) + bb.w;
        *(float4*)(Cbase + 1 * G3) = o;
    }
    {
        float4 o;
        o.x = f2lo(c20) + bb.x; o.y = f2hi(c20) + bb.y;
        o.z = f2lo(c21) + bb.z; o.w = f2hi(c21) + bb.w;
        *(float4*)(Cbase + 2 * G3) = o;
    }
    {
        float4 o;
        o.x = f2lo(c30) + bb.x; o.y = f2hi(c30) + bb.y;
        o.z = f2lo(c31) + bb.z; o.w = f2hi(c31) + bb.w;
        *(float4*)(Cbase + 3 * G3) = o;
    }
}

// ---------------------------------------------------------------------------
// Recurrence: cluster of 4 CTAs handles 4 batch sequences.
// CTA rank k owns h-units [64k, 64k+64): keeps W_hh rows {u, 256+u, 512+u} in smem.
// Per step: each thread (u_loc = tid>>2, b_loc = tid&3) computes hr/hz/hn dots
// over the full h (256) from smem, applies GRU gates, then DSMEM-broadcasts the
// new h value to all 4 CTAs' next h buffer, followed by barrier.cluster.
// Double-buffered h state; one cluster barrier per step gives the needed
// release/acquire ordering for the st.shared::cluster writes.
// ---------------------------------------------------------------------------
__global__ __launch_bounds__(256, 1) __cluster_dims__(4, 1, 1)
void gru_recur(const float* __restrict__ Whh, const float* __restrict__ bhh,
               float* __restrict__ outA, int ldA,
               float* __restrict__ outB, int ldB)
{
    extern __shared__ __align__(16) float sm[];
    float* sW = sm;                       // [192][LDW]
    float* sB = sm + 192 * LDW;           // [192]
    float* sH = sm + 192 * LDW + 192;     // [2][4][LDW]

    const int tid = threadIdx.x;
    uint32_t rank;
    asm("mov.u32 %0, %%cluster_ctarank;" : "=r"(rank));
    const int u_loc = tid >> 2;           // 0..63
    const int b_loc = tid & 3;            // 0..3
    const int u_glob = (int)rank * 64 + u_loc;
    const int batch = (blockIdx.x >> 2) * 4 + b_loc;

    // Load this CTA's W_hh slice (rows g*256 + rank*64 + u) into smem, padded.
    for (int idx = tid; idx < 192 * 64; idx += 256) {
        int r = idx >> 6, k4 = idx & 63;
        int g = r >> 6, u = r & 63;
        int grow = g * 256 + (int)rank * 64 + u;
        float4 v = ((const float4*)(Whh + (size_t)grow * 256))[k4];
        ((float4*)(sW + (size_t)r * LDW))[k4] = v;
    }
    if (tid < 192) {
        int g = tid >> 6, u = tid & 63;
        sB[tid] = bhh[g * 256 + (int)rank * 64 + u];
    }
    for (int i = tid; i < 2 * 4 * LDW; i += 256) sH[i] = 0.f;
    __syncthreads();
    asm volatile("barrier.cluster.arrive.aligned;" ::: "memory");
    asm volatile("barrier.cluster.wait.aligned;" ::: "memory");

    const ulonglong2* wr = (const ulonglong2*)(sW + (size_t)(u_loc) * LDW);
    const ulonglong2* wz = (const ulonglong2*)(sW + (size_t)(64 + u_loc) * LDW);
    const ulonglong2* wn = (const ulonglong2*)(sW + (size_t)(128 + u_loc) * LDW);
    const float bhr = sB[u_loc], bhz = sB[64 + u_loc], bhn = sB[128 + u_loc];

    const float* xgp = g_xg + ((size_t)batch * Sz) * G3 + u_glob;
    size_t oa = ((size_t)batch * Sz) * (size_t)ldA + u_glob;
    size_t ob = ((size_t)batch * Sz) * (size_t)ldB + u_glob;

    uint32_t sH_u32;
    {
        uint32_t b_;
        asm("{ .reg .u64 t; cvta.to.shared.u64 t, %1; cvt.u32.u64 %0, t; }"
            : "=r"(b_) : "l"(sm));
        sH_u32 = b_ + (uint32_t)((192 * LDW + 192) * 4);
    }

    int cur = 0;
    for (int s = 0; s < Sz; ++s) {
        // Input-side gate values (global, streamed; latency hidden by dot loop)
        const float xr = __ldg(xgp);
        const float xz = __ldg(xgp + 256);
        const float xn = __ldg(xgp + 512);

        const ulonglong2* hv = (const ulonglong2*)(sH + (size_t)(cur * 4 + b_loc) * LDW);
        u64 ar = 0, az = 0, an = 0;
#pragma unroll 8
        for (int kk = 0; kk < 64; ++kk) {
            ulonglong2 h4 = hv[kk];
            ulonglong2 w;
            w = wr[kk]; ar = fma2(w.x, h4.x, ar); ar = fma2(w.y, h4.y, ar);
            w = wz[kk]; az = fma2(w.x, h4.x, az); az = fma2(w.y, h4.y, az);
            w = wn[kk]; an = fma2(w.x, h4.x, an); an = fma2(w.y, h4.y, an);
        }
        const float hr = f2lo(ar) + f2hi(ar) + bhr;
        const float hz = f2lo(az) + f2hi(az) + bhz;
        const float hn = f2lo(an) + f2hi(an) + bhn;
        const float hprev = sH[(size_t)(cur * 4 + b_loc) * LDW + u_glob];

        const float rg = 1.f / (1.f + expf(-(xr + hr)));
        const float zg = 1.f / (1.f + expf(-(xz + hz)));
        const float ng = tanhf(xn + rg * hn);
        const float hnew = ng + zg * (hprev - ng);

        // Broadcast new h value into all 4 CTAs' next-step buffer.
        const uint32_t loff =
            sH_u32 + (uint32_t)((((cur ^ 1) * 4 + b_loc) * LDW + u_glob) * 4);
#pragma unroll
        for (int p = 0; p < 4; ++p) {
            uint32_t ra;
            asm("mapa.shared::cluster.u32 %0, %1, %2;" : "=r"(ra) : "r"(loff), "r"(p));
            asm volatile("st.shared::cluster.f32 [%0], %1;" :: "r"(ra), "f"(hnew) : "memory");
        }

        outA[oa] = hnew;
        if (outB) outB[ob] = hnew;
        oa += (size_t)ldA;
        ob += (size_t)ldB;
        xgp += G3;

        // Release my DSMEM writes / acquire peers' writes for next step.
        asm volatile("barrier.cluster.arrive.aligned;" ::: "memory");
        asm volatile("barrier.cluster.wait.aligned;" ::: "memory");
        cur ^= 1;
    }
}

// ---------------------------------------------------------------------------
// Launch: gemm(xg0) -> recur L0 (h1 into concat[:, :, 0:256])
//         gemm(xg1 from h1) -> recur L1 (h2 into out_h2 and concat[:, :, 256:512])
// Output layout assumed: [h2 (B,S,H)] then [concat(h1,h2) (B,S,2H)].
// ---------------------------------------------------------------------------
extern "C" void kernel_launch(void* const* d_in, const int* in_sizes, int n_in,
                              void* d_out, int out_size)
{
    (void)in_sizes; (void)n_in; (void)out_size;
    const float* inputs = (const float*)d_in[0];
    const float* W_ih0  = (const float*)d_in[1];
    const float* W_hh0  = (const float*)d_in[2];
    const float* b_ih0  = (const float*)d_in[3];
    const float* b_hh0  = (const float*)d_in[4];
    const float* W_ih1  = (const float*)d_in[5];
    const float* W_hh1  = (const float*)d_in[6];
    const float* b_ih1  = (const float*)d_in[7];
    const float* b_hh1  = (const float*)d_in[8];

    float* out_h2  = (float*)d_out;                            // [B,S,H]
    float* out_cat = out_h2 + (size_t)Bz * Sz * Hz;            // [B,S,2H]

    // Idempotent, deterministic; executes immediately (not a stream op) even
    // under capture.
    cudaFuncSetAttribute(gru_recur, cudaFuncAttributeMaxDynamicSharedMemorySize,
                         SMEM_BYTES);

    dim3 ggrid(G3 / 64, (Bz * Sz) / 64);  // (12, 1024)

    // Layer 0
    gemm_nt_bias<<<ggrid, 256>>>(inputs, 256, W_ih0, b_ih0);
    gru_recur<<<64, 256, SMEM_BYTES>>>(W_hh0, b_hh0,
                                       out_cat, 2 * Hz,        // h1 -> concat[:, :, 0:H]
                                       nullptr, 0);
    // Layer 1 (input = h1, strided inside concat)
    gemm_nt_bias<<<ggrid, 256>>>(out_cat, 2 * Hz, W_ih1, b_ih1);
    gru_recur<<<64, 256, SMEM_BYTES>>>(W_hh1, b_hh1,
                                       out_cat + Hz, 2 * Hz,   // h2 -> concat[:, :, H:2H]
                                       out_h2, Hz);            // h2 -> primary output
}